// round 14
// baseline (speedup 1.0000x reference)
#include <cuda_runtime.h>
#include <cuda_bf16.h>
#include <math.h>

#define SEQ    2048
#define EMB    1024
#define STATE  1024
#define QIN    2048
#define QUERY  256
#define NKB    10000
#define NKBP   10240
#define VALUE  512
#define NTOK   32000
#define DECIN  2560
#define GATES  4096
#define LIN    1536

#define NBLK   148
#define NTHR   512
#define NWTOT  (NBLK * 16)

// ---------------- device global scratch (static allocation only) ----------------
__device__ __align__(16) float d_OUT[SEQ * DECIN];          // [emb | val | hx_pre]
__device__ __align__(16) float d_PQ[SEQ * QIN];
__device__ __align__(16) float d_PI[SEQ * GATES];
__device__ __align__(16) float d_Wq1T[QIN * QIN];           // fp32, PQ GEMM only
__device__ __align__(16) float d_bihh[GATES];
__device__ __align__(16) float d_hx[2][STATE];
__device__ __align__(16) float d_cx[STATE];
__device__ __align__(16) float d_qh[QIN];
__device__ __align__(16) float d_qv[QUERY];
__device__ __align__(16) float d_w[NKBP];
__device__ __align__(16) float d_valU[VALUE + 4];
__device__ __align__(16) float d_ghx[GATES];
// bf16 recurrent weights (prepped once)
__device__ __align__(16) __nv_bfloat16 d_Wq1B[QIN * STATE];        // [r][k]=Wq1[k][r], k<1024
__device__ __align__(16) __nv_bfloat16 d_WhhB[GATES * STATE];      // = W_hh
__device__ __align__(16) __nv_bfloat16 d_Wq2B[QUERY * QIN];        // [k][j]=Wq2[j][k]
__device__ __align__(16) __nv_bfloat16 d_kkB[NKB * QUERY];         // = kb_keys
__device__ __align__(16) __nv_bfloat16 d_WivB[STATE * 4 * VALUE];  // [i][g][v]=W_ih[g*1024+i][1024+v]
__device__ __align__(16) __nv_bfloat16 d_kbvB[(VALUE + 1) * NKBP]; // [v][n]; row 512 = ones
// bf16 decoder operands
__device__ __align__(16) __nv_bfloat16 d_Abf[SEQ * DECIN];
__device__ __align__(16) __nv_bfloat16 d_Wdbf[NTOK * DECIN];

__device__ unsigned d_flags[NBLK];

// ---------------- helpers ----------------
__device__ __forceinline__ float wred(float v) {
#pragma unroll
    for (int o = 16; o; o >>= 1) v += __shfl_xor_sync(0xffffffffu, v, o);
    return v;
}

// dot of 8 bf16 weights (packed uint4) with 8 fp32 activations (two float4)
__device__ __forceinline__ float dot8(uint4 wv, float4 x0, float4 x1) {
    float2 f0 = __bfloat1622float2(*(__nv_bfloat162*)&wv.x);
    float2 f1 = __bfloat1622float2(*(__nv_bfloat162*)&wv.y);
    float2 f2 = __bfloat1622float2(*(__nv_bfloat162*)&wv.z);
    float2 f3 = __bfloat1622float2(*(__nv_bfloat162*)&wv.w);
    return f0.x * x0.x + f0.y * x0.y + f1.x * x0.z + f1.y * x0.w
         + f2.x * x1.x + f2.y * x1.y + f3.x * x1.z + f3.y * x1.w;
}

// All-poll flag barrier: each block release-stores its own flag (parallel,
// distinct addresses — no atomic serialization); EVERY block's warp 0 polls
// all 148 flags with relaxed loads (MLP=5), then one acquire fence.
// No central releaser, no second hop. Flags are monotonic generations.
__device__ __forceinline__ void gridbar(unsigned &mygen) {
    ++mygen;
    __syncthreads();
    if (threadIdx.x < 32) {
        if (threadIdx.x == 0)
            asm volatile("st.release.gpu.global.u32 [%0], %1;"
                         :: "l"(&d_flags[blockIdx.x]), "r"(mygen) : "memory");
        bool done = false;
        while (!done) {
            unsigned mn = 0xffffffffu;
#pragma unroll
            for (int i = 0; i < 5; ++i) {
                int b = (int)threadIdx.x + i * 32;
                if (b < NBLK) {
                    unsigned f;
                    asm volatile("ld.relaxed.gpu.global.u32 %0, [%1];"
                                 : "=r"(f) : "l"(&d_flags[b]) : "memory");
                    mn = min(mn, f);
                }
            }
            done = __all_sync(0xffffffffu, (int)(mn >= mygen));
        }
        if (threadIdx.x == 0)
            asm volatile("fence.acq_rel.gpu;" ::: "memory");
    }
    __syncthreads();
}

// ---------------- init: state, pads, fused bias, barrier reset ----------------
__global__ void init_k(const float* __restrict__ b_ih, const float* __restrict__ b_hh) {
    int i = blockIdx.x * blockDim.x + threadIdx.x;
    if (i < NBLK) d_flags[i] = 0u;
    if (i < STATE) { d_hx[0][i] = 0.f; d_hx[1][i] = 0.f; d_cx[i] = 0.f; }
    if (i < GATES) d_bihh[i] = b_ih[i] + b_hh[i];
    if (i < (NKBP - NKB)) d_w[NKB + i] = 0.f;
    if (i < (VALUE + 1) * (NKBP - NKB)) {
        int v = i / (NKBP - NKB);
        int n = NKB + i % (NKBP - NKB);
        d_kbvB[(size_t)v * NKBP + n] = __float2bfloat16(0.f);
    }
    if (i < NKB) d_kbvB[(size_t)VALUE * NKBP + i] = __float2bfloat16(1.f);
}

// ---------------- embedding gather ----------------
__global__ void embed_k(const int* __restrict__ ids, const float* __restrict__ encW) {
    int i = blockIdx.x * blockDim.x + threadIdx.x;
    if (i < SEQ * EMB) {
        int s = i >> 10, e = i & 1023;
        d_OUT[(size_t)s * DECIN + e] = encW[(size_t)ids[s] * EMB + e];
    }
}

// ---------------- fused one-time prep: transposes + bf16 conversions ----------------
__global__ void prep_k(const float* __restrict__ Wq1, const float* __restrict__ Wq2,
                       const float* __restrict__ kb_vals, const float* __restrict__ W_dec,
                       const float* __restrict__ kb_keys, const float* __restrict__ W_ih,
                       const float* __restrict__ W_hh) {
    const long stride = (long)gridDim.x * blockDim.x;
    const long t0 = (long)blockIdx.x * blockDim.x + threadIdx.x;
    // 1) Wq1T fp32 (PQ GEMM)
    for (long j = t0; j < (long)QIN * QIN; j += stride) {
        int r = (int)(j >> 11), c = (int)(j & (QIN - 1));
        d_Wq1T[j] = Wq1[(size_t)c * QIN + r];
    }
    // 2) Wq1B bf16: [r][k] = Wq1[k][r], k < 1024
    for (long j = t0; j < (long)QIN * STATE; j += stride) {
        int r = (int)(j >> 10), k = (int)(j & (STATE - 1));
        d_Wq1B[j] = __float2bfloat16(Wq1[(size_t)k * QIN + r]);
    }
    // 3) WhhB bf16 (no transpose)
    for (long j = t0; j < (long)GATES * STATE; j += stride)
        d_WhhB[j] = __float2bfloat16(W_hh[j]);
    // 4) Wq2B bf16: [k][jj] = Wq2[jj][k]
    for (long j = t0; j < (long)QUERY * QIN; j += stride) {
        int k = (int)(j >> 11), jj = (int)(j & (QIN - 1));
        d_Wq2B[j] = __float2bfloat16(Wq2[(size_t)jj * QUERY + k]);
    }
    // 5) kkB bf16 (no transpose)
    for (long j = t0; j < (long)NKB * QUERY; j += stride)
        d_kkB[j] = __float2bfloat16(kb_keys[j]);
    // 6) WivB bf16: [i][g][v] = W_ih[g*1024 + i][1024 + v]
    for (long j = t0; j < (long)STATE * 4 * VALUE; j += stride) {
        int i = (int)(j >> 11);
        int rem = (int)(j & 2047);
        int g = rem >> 9, v = rem & 511;
        d_WivB[j] = __float2bfloat16(W_ih[(size_t)(g * STATE + i) * LIN + EMB + v]);
    }
    // 7) kbvB bf16: [v][n] = kb_vals[n][v]
    for (long j = t0; j < (long)VALUE * NKB; j += stride) {
        int v = (int)(j / NKB), n = (int)(j % NKB);
        d_kbvB[(size_t)v * NKBP + n] = __float2bfloat16(kb_vals[(size_t)n * VALUE + v]);
    }
    // 8) W_dec -> bf16
    const float2* s2 = (const float2*)W_dec;
    __nv_bfloat162* dd = (__nv_bfloat162*)d_Wdbf;
    for (long j = t0; j < (long)NTOK * DECIN / 2; j += stride)
        dd[j] = __float22bfloat162_rn(s2[j]);
}

// ---------------- fp32 -> bf16 conversion (n even) ----------------
__global__ void tobf16_k(const float* __restrict__ S, __nv_bfloat16* __restrict__ D, long n) {
    const float2* s2 = (const float2*)S;
    __nv_bfloat162* d2 = (__nv_bfloat162*)D;
    long half = n >> 1;
    for (long j = (long)blockIdx.x * blockDim.x + threadIdx.x; j < half;
         j += (long)gridDim.x * blockDim.x)
        d2[j] = __float22bfloat162_rn(s2[j]);
}

// ---------------- fp32 SIMT SGEMM (phase-A only): C = bias + A @ B^T ----------------
__global__ void __launch_bounds__(256) gemm_abt(
    const float* __restrict__ A, int lda,
    const float* __restrict__ B, int ldb,
    const float* __restrict__ bias,
    float* __restrict__ C, int ldc, int K)
{
    __shared__ float As[16][132];
    __shared__ float Bs[16][132];
    const int tid = threadIdx.x;
    const int m0 = blockIdx.x * 128, n0 = blockIdx.y * 128;
    const int lr = tid >> 2;
    const int lk = (tid & 3) * 4;
    const int tx = tid & 15, ty = tid >> 4;

    float acc[8][8];
#pragma unroll
    for (int i = 0; i < 8; ++i)
#pragma unroll
        for (int j = 0; j < 8; ++j) acc[i][j] = 0.f;

    for (int k0 = 0; k0 < K; k0 += 16) {
#pragma unroll
        for (int h = 0; h < 2; ++h) {
            int r = lr + h * 64;
            float4 a = *(const float4*)&A[(size_t)(m0 + r) * lda + k0 + lk];
            As[lk + 0][r] = a.x; As[lk + 1][r] = a.y;
            As[lk + 2][r] = a.z; As[lk + 3][r] = a.w;
            float4 b = *(const float4*)&B[(size_t)(n0 + r) * ldb + k0 + lk];
            Bs[lk + 0][r] = b.x; Bs[lk + 1][r] = b.y;
            Bs[lk + 2][r] = b.z; Bs[lk + 3][r] = b.w;
        }
        __syncthreads();
#pragma unroll
        for (int kk = 0; kk < 16; ++kk) {
            float av[8], bv[8];
            const float4* a4 = (const float4*)&As[kk][ty * 8];
            const float4* b4 = (const float4*)&Bs[kk][tx * 8];
            float4 a0 = a4[0], a1 = a4[1];
            float4 b0 = b4[0], b1 = b4[1];
            av[0] = a0.x; av[1] = a0.y; av[2] = a0.z; av[3] = a0.w;
            av[4] = a1.x; av[5] = a1.y; av[6] = a1.z; av[7] = a1.w;
            bv[0] = b0.x; bv[1] = b0.y; bv[2] = b0.z; bv[3] = b0.w;
            bv[4] = b1.x; bv[5] = b1.y; bv[6] = b1.z; bv[7] = b1.w;
#pragma unroll
            for (int i = 0; i < 8; ++i)
#pragma unroll
                for (int j = 0; j < 8; ++j) acc[i][j] += av[i] * bv[j];
        }
        __syncthreads();
    }
#pragma unroll
    for (int i = 0; i < 8; ++i) {
        int row = m0 + ty * 8 + i;
#pragma unroll
        for (int j = 0; j < 8; ++j) {
            int col = n0 + tx * 8 + j;
            C[(size_t)row * ldc + col] = acc[i][j] + __ldg(&bias[col]);
        }
    }
}

// ---------------- bf16 tensor-core GEMM (decoder) ----------------
__global__ void __launch_bounds__(256) gemm_bf16_mma(
    const __nv_bfloat16* __restrict__ A, int lda,
    const __nv_bfloat16* __restrict__ B, int ldb,
    const float* __restrict__ bias,
    float* __restrict__ C, int ldc, int K)
{
    __shared__ unsigned As[128][17];
    __shared__ unsigned Bs[128][17];
    const int tid = threadIdx.x;
    const int wid = tid >> 5, lane = tid & 31;
    const int wm = wid & 3, wn = wid >> 2;
    const int m0 = blockIdx.x * 128, n0 = blockIdx.y * 128;
    const int r = lane >> 2, kp = lane & 3;

    float acc[2][8][4];
#pragma unroll
    for (int mt = 0; mt < 2; ++mt)
#pragma unroll
        for (int nt = 0; nt < 8; ++nt)
#pragma unroll
            for (int c = 0; c < 4; ++c) acc[mt][nt][c] = 0.f;

    for (int k0 = 0; k0 < K; k0 += 32) {
#pragma unroll
        for (int i = 0; i < 2; ++i) {
            int idx = tid + i * 256;
            int row = idx >> 2, q = idx & 3;
            uint4 va = *(const uint4*)&A[(size_t)(m0 + row) * lda + k0 + q * 8];
            As[row][q * 4 + 0] = va.x; As[row][q * 4 + 1] = va.y;
            As[row][q * 4 + 2] = va.z; As[row][q * 4 + 3] = va.w;
            uint4 vb = *(const uint4*)&B[(size_t)(n0 + row) * ldb + k0 + q * 8];
            Bs[row][q * 4 + 0] = vb.x; Bs[row][q * 4 + 1] = vb.y;
            Bs[row][q * 4 + 2] = vb.z; Bs[row][q * 4 + 3] = vb.w;
        }
        __syncthreads();
#pragma unroll
        for (int kk = 0; kk < 2; ++kk) {
            const int kb = kk * 8;
            unsigned afr[2][4];
#pragma unroll
            for (int mt = 0; mt < 2; ++mt) {
                int row = wm * 32 + mt * 16 + r;
                afr[mt][0] = As[row][kb + kp];
                afr[mt][1] = As[row + 8][kb + kp];
                afr[mt][2] = As[row][kb + kp + 4];
                afr[mt][3] = As[row + 8][kb + kp + 4];
            }
#pragma unroll
            for (int nt = 0; nt < 8; ++nt) {
                int brow = wn * 64 + nt * 8 + r;
                unsigned b0 = Bs[brow][kb + kp];
                unsigned b1 = Bs[brow][kb + kp + 4];
#pragma unroll
                for (int mt = 0; mt < 2; ++mt) {
                    asm volatile(
                        "mma.sync.aligned.m16n8k16.row.col.f32.bf16.bf16.f32 "
                        "{%0,%1,%2,%3}, {%4,%5,%6,%7}, {%8,%9}, {%0,%1,%2,%3};"
                        : "+f"(acc[mt][nt][0]), "+f"(acc[mt][nt][1]),
                          "+f"(acc[mt][nt][2]), "+f"(acc[mt][nt][3])
                        : "r"(afr[mt][0]), "r"(afr[mt][1]),
                          "r"(afr[mt][2]), "r"(afr[mt][3]),
                          "r"(b0), "r"(b1));
                }
            }
        }
        __syncthreads();
    }
#pragma unroll
    for (int mt = 0; mt < 2; ++mt) {
#pragma unroll
        for (int nt = 0; nt < 8; ++nt) {
            int row = m0 + wm * 32 + mt * 16 + r;
            int col = n0 + wn * 64 + nt * 8 + 2 * kp;
            float b0 = __ldg(&bias[col]), b1 = __ldg(&bias[col + 1]);
            *(float2*)&C[(size_t)row * ldc + col] =
                make_float2(acc[mt][nt][0] + b0, acc[mt][nt][1] + b1);
            *(float2*)&C[(size_t)(row + 8) * ldc + col] =
                make_float2(acc[mt][nt][2] + b0, acc[mt][nt][3] + b1);
        }
    }
}

// ---------------- persistent recurrence kernel (bf16 weights) ----------------
__global__ void __launch_bounds__(NTHR, 1) recur_k(const float* __restrict__ bq2)
{
    __shared__ __align__(16) float sb[NKBP];   // 40 KB staging buffer
    float4* sb4 = (float4*)sb;
    const int tid  = threadIdx.x;
    const int lane = tid & 31;
    const int wrp  = tid >> 5;
    const int W    = blockIdx.x * 16 + wrp;
    const int gid  = blockIdx.x * NTHR + tid;
    unsigned mygen = 0;

    for (int t = 0; t < SEQ; ++t) {
        const int p = t & 1;

        // ======== stage A: qh = tanh(PQ + hx@Wq1_hx); ghx = hx@W_hh.T ========
        if (tid < STATE / 4) sb4[tid] = __ldcg((const float4*)&d_hx[p][0] + tid);
        if (gid < QUERY)     d_qv[gid]   = 0.f;
        if (gid < VALUE + 1) d_valU[gid] = 0.f;
        __syncthreads();
        {
            const float* pq = d_PQ + (size_t)t * QIN;
            for (int r = W; r < QIN + GATES; r += NWTOT) {
                const uint4* wr4 = (r < QIN)
                    ? (const uint4*)(d_Wq1B + (size_t)r * STATE)
                    : (const uint4*)(d_WhhB + (size_t)(r - QIN) * STATE);
                float s = 0.f;
#pragma unroll
                for (int u = 0; u < 4; ++u) {
                    uint4 wv = __ldcg(&wr4[u * 32 + lane]);
                    int fi = (u * 32 + lane) * 2;
                    s += dot8(wv, sb4[fi], sb4[fi + 1]);
                }
                s = wred(s);
                if (lane == 0) {
                    if (r < QIN) __stcg(&d_qh[r], tanhf(__ldcg(&pq[r]) + s));
                    else         __stcg(&d_ghx[r - QIN], s);
                }
            }
        }
        gridbar(mygen);

        // ======== stage B: q = qh @ Wq2 + bq2 (8 x 256 chunks) ========
        for (int i = tid; i < QIN / 4; i += NTHR) sb4[i] = __ldcg((const float4*)d_qh + i);
        __syncthreads();
        for (int task = W; task < QUERY * 8; task += NWTOT) {
            int k = task >> 3, c = task & 7;
            const uint4* wr4 = (const uint4*)(d_Wq2B + (size_t)k * QIN + c * 256);
            uint4 wv = __ldcg(&wr4[lane]);
            int fi = c * 64 + lane * 2;
            float s = dot8(wv, sb4[fi], sb4[fi + 1]);
            s = wred(s);
            if (lane == 0) {
                if (c == 0) s += __ldg(&bq2[k]);
                atomicAdd(&d_qv[k], s);
            }
        }
        gridbar(mygen);

        // ======== stage C: w[n] = exp(kkB[n] . q) (logits O(10), no max shift) ========
        if (tid < QUERY / 4) sb4[tid] = __ldcg((const float4*)d_qv + tid);
        __syncthreads();
        for (int n = W; n < NKB; n += NWTOT) {
            const uint4* kr4 = (const uint4*)(d_kkB + (size_t)n * QUERY);
            uint4 wv = __ldcg(&kr4[lane]);
            int fi = lane * 2;
            float s = dot8(wv, sb4[fi], sb4[fi + 1]);
            s = wred(s);
            if (lane == 0) __stcg(&d_w[n], expf(s));
        }
        gridbar(mygen);

        // ======== stage D: valU[v] = w . kbvB[v]; valU[512] = sum w ========
        for (int i = tid; i < NKBP / 4; i += NTHR) sb4[i] = __ldcg((const float4*)d_w + i);
        __syncthreads();
        for (int task = W; task < (VALUE + 1) * 8; task += NWTOT) {
            int v = task >> 3, c = task & 7;
            const uint4* kr4 = (const uint4*)(d_kbvB + (size_t)v * NKBP + c * 1280);
            float s = 0.f;
#pragma unroll
            for (int u = 0; u < 5; ++u) {
                uint4 wv = __ldcg(&kr4[u * 32 + lane]);
                int fi = c * 320 + (u * 32 + lane) * 2;
                s += dot8(wv, sb4[fi], sb4[fi + 1]);
            }
            s = wred(s);
            if (lane == 0) atomicAdd(&d_valU[v], s);
        }
        gridbar(mygen);

        // ======== stage E: gates + LSTM pointwise + write OUT row ========
        if (tid < VALUE / 4) sb4[tid] = __ldcg((const float4*)d_valU + tid);
        if (tid == NTHR - 1) sb[VALUE] = __ldcg(&d_valU[VALUE]);
        __syncthreads();
        {
            const float inv = 1.f / sb[VALUE];
            float* outrow = d_OUT + (size_t)t * DECIN;
            const float* pi = d_PI + (size_t)t * GATES;
            for (int task = W; task < STATE + 16; task += NWTOT) {
                if (task < STATE) {
                    const int i = task;
                    const uint4* row = (const uint4*)(d_WivB + (size_t)i * 4 * VALUE);
                    float gs[4];
#pragma unroll
                    for (int g = 0; g < 4; ++g) {
                        float s = 0.f;
#pragma unroll
                        for (int u = 0; u < 2; ++u) {
                            uint4 wv = __ldcg(&row[g * 64 + u * 32 + lane]);
                            int fi = (u * 32 + lane) * 2;
                            s += dot8(wv, sb4[fi], sb4[fi + 1]);
                        }
                        gs[g] = wred(s);
                    }
                    if (lane == 0) {
                        float gi = __ldcg(&pi[i])             + __ldcg(&d_ghx[i])             + gs[0] * inv;
                        float gf = __ldcg(&pi[i + STATE])     + __ldcg(&d_ghx[i + STATE])     + gs[1] * inv;
                        float gG = __ldcg(&pi[i + 2 * STATE]) + __ldcg(&d_ghx[i + 2 * STATE]) + gs[2] * inv;
                        float go = __ldcg(&pi[i + 3 * STATE]) + __ldcg(&d_ghx[i + 3 * STATE]) + gs[3] * inv;
                        float hpre = __ldcg(&d_hx[p][i]);
                        float ii = 1.f / (1.f + expf(-gi));
                        float ff = 1.f / (1.f + expf(-gf));
                        float g2 = tanhf(gG);
                        float oo = 1.f / (1.f + expf(-go));
                        float cn = ff * __ldcg(&d_cx[i]) + ii * g2;
                        float hn = oo * tanhf(cn);
                        __stcg(&d_cx[i], cn);
                        __stcg(&d_hx[1 - p][i], hn);
                        outrow[EMB + VALUE + i] = hpre;
                    }
                } else {
                    int vb = (task - STATE) * 32 + lane;   // 16 warps x 32 = 512
                    outrow[EMB + vb] = sb[vb] * inv;
                }
            }
        }
        gridbar(mygen);
    }
}

// ---------------- row-wise log-softmax (in place) ----------------
__global__ void __launch_bounds__(256) logsoftmax_k(float* __restrict__ X) {
    const int row = blockIdx.x;
    float* x = X + (size_t)row * NTOK;
    __shared__ float sred[8];
    const int tid = threadIdx.x, lane = tid & 31, w = tid >> 5;

    float m = -1e30f;
    for (int i = tid; i < NTOK; i += 256) m = fmaxf(m, x[i]);
#pragma unroll
    for (int o = 16; o; o >>= 1) m = fmaxf(m, __shfl_xor_sync(0xffffffffu, m, o));
    if (lane == 0) sred[w] = m;
    __syncthreads();
    if (tid == 0) {
        float v = sred[0];
#pragma unroll
        for (int j = 1; j < 8; ++j) v = fmaxf(v, sred[j]);
        sred[0] = v;
    }
    __syncthreads();
    m = sred[0];
    __syncthreads();

    float s = 0.f;
    for (int i = tid; i < NTOK; i += 256) s += expf(x[i] - m);
    s = wred(s);
    if (lane == 0) sred[w] = s;
    __syncthreads();
    if (tid == 0) {
        float v = 0.f;
#pragma unroll
        for (int j = 0; j < 8; ++j) v += sred[j];
        sred[0] = v;
    }
    __syncthreads();
    const float lse = m + logf(sred[0]);

    for (int i = tid; i < NTOK; i += 256) x[i] = x[i] - lse;
}

// ---------------- launch ----------------
extern "C" void kernel_launch(void* const* d_in, const int* in_sizes, int n_in,
                              void* d_out, int out_size) {
    const int*   ids     = (const int*)  d_in[0];
    const float* enc_W   = (const float*)d_in[1];
    const float* Wq1     = (const float*)d_in[2];
    const float* bq1     = (const float*)d_in[3];
    const float* Wq2     = (const float*)d_in[4];
    const float* bq2     = (const float*)d_in[5];
    const float* kb_keys = (const float*)d_in[6];
    const float* kb_vals = (const float*)d_in[7];
    const float* W_ih    = (const float*)d_in[8];
    const float* b_ih    = (const float*)d_in[9];
    const float* W_hh    = (const float*)d_in[10];
    const float* b_hh    = (const float*)d_in[11];
    const float* W_dec   = (const float*)d_in[12];
    const float* b_dec   = (const float*)d_in[13];
    float* out = (float*)d_out;

    float* wq1t_dev = nullptr; cudaGetSymbolAddress((void**)&wq1t_dev, d_Wq1T);
    float* out_dev  = nullptr; cudaGetSymbolAddress((void**)&out_dev,  d_OUT);
    float* pq_dev   = nullptr; cudaGetSymbolAddress((void**)&pq_dev,   d_PQ);
    float* pi_dev   = nullptr; cudaGetSymbolAddress((void**)&pi_dev,   d_PI);
    float* bihh_dev = nullptr; cudaGetSymbolAddress((void**)&bihh_dev, d_bihh);
    __nv_bfloat16* abf_dev = nullptr; cudaGetSymbolAddress((void**)&abf_dev, d_Abf);
    __nv_bfloat16* wdb_dev = nullptr; cudaGetSymbolAddress((void**)&wdb_dev, d_Wdbf);

    // 1) init (state zero, pads, ones row, fused bias, barrier reset)
    init_k<<<((VALUE + 1) * (NKBP - NKB) + 255) / 256, 256>>>(b_ih, b_hh);
    // 2) embedding gather
    embed_k<<<(SEQ * EMB + 255) / 256, 256>>>(ids, enc_W);
    // 3) fused prep: fp32 transpose + all bf16 weight conversions
    prep_k<<<2048, 256>>>(Wq1, Wq2, kb_vals, W_dec, kb_keys, W_ih, W_hh);
    // 4) PQ = emb @ Wq1[x-part] + bq1
    gemm_abt<<<dim3(SEQ / 128, QIN / 128), 256>>>(
        out_dev, DECIN, wq1t_dev + EMB, QIN, bq1, pq_dev, QIN, EMB);
    // 5) PI = emb @ W_ih[:, :1024].T + (b_ih + b_hh)
    gemm_abt<<<dim3(SEQ / 128, GATES / 128), 256>>>(
        out_dev, DECIN, W_ih, LIN, bihh_dev, pi_dev, GATES, EMB);
    // 6) persistent recurrence (all weights prepped into device globals)
    recur_k<<<NBLK, NTHR>>>(bq2);
    // 7) OUT -> bf16, then tensor-core decoder GEMM
    tobf16_k<<<2048, 256>>>(out_dev, abf_dev, (long)SEQ * DECIN);
    gemm_bf16_mma<<<dim3(SEQ / 128, NTOK / 128), 256>>>(
        abf_dev, DECIN, wdb_dev, DECIN, b_dec, out, NTOK, DECIN);
    // 8) log-softmax in place
    logsoftmax_k<<<SEQ, 256>>>(out);
}

// round 15
// speedup vs baseline: 1.2459x; 1.2459x over previous
#include <cuda_runtime.h>
#include <cuda_bf16.h>
#include <math.h>

#define SEQ    2048
#define EMB    1024
#define STATE  1024
#define QIN    2048
#define QUERY  256
#define NKB    10000
#define NKBP   10240
#define VALUE  512
#define NTOK   32000
#define DECIN  2560
#define GATES  4096
#define LIN    1536

#define NBLK   148
#define NTHR   512
#define NWTOT  (NBLK * 16)

// ---------------- device global scratch (static allocation only) ----------------
__device__ __align__(16) float d_OUT[SEQ * DECIN];          // [emb | val | hx_pre]
__device__ __align__(16) float d_PQ[SEQ * QIN];
__device__ __align__(16) float d_PI[SEQ * GATES];
__device__ __align__(16) float d_Wq1T[QIN * QIN];           // fp32, PQ GEMM only
__device__ __align__(16) float d_bihh[GATES];
__device__ __align__(16) float d_hx[2][STATE];
__device__ __align__(16) float d_cx[STATE];
__device__ __align__(16) float d_qh[QIN];
__device__ __align__(16) float d_qv[QUERY];
__device__ __align__(16) float d_w[NKBP];
__device__ __align__(16) float d_valU[VALUE + 4];
__device__ __align__(16) float d_ghx[GATES];
// bf16 recurrent weights (prepped once)
__device__ __align__(16) __nv_bfloat16 d_Wq1B[QIN * STATE];        // [r][k]=Wq1[k][r], k<1024
__device__ __align__(16) __nv_bfloat16 d_WhhB[GATES * STATE];      // = W_hh
__device__ __align__(16) __nv_bfloat16 d_Wq2B[QUERY * QIN];        // [k][j]=Wq2[j][k]
__device__ __align__(16) __nv_bfloat16 d_kkB[NKB * QUERY];         // = kb_keys
__device__ __align__(16) __nv_bfloat16 d_WivB[STATE * 4 * VALUE];  // [i][g][v]=W_ih[g*1024+i][1024+v]
__device__ __align__(16) __nv_bfloat16 d_kbvB[(VALUE + 1) * NKBP]; // [v][n]; row 512 = ones
// bf16 decoder operands
__device__ __align__(16) __nv_bfloat16 d_Abf[SEQ * DECIN];
__device__ __align__(16) __nv_bfloat16 d_Wdbf[NTOK * DECIN];

__device__ unsigned d_cnt;
__device__ unsigned d_gen;

// ---------------- helpers ----------------
__device__ __forceinline__ float wred(float v) {
#pragma unroll
    for (int o = 16; o; o >>= 1) v += __shfl_xor_sync(0xffffffffu, v, o);
    return v;
}

// dot of 8 bf16 weights (packed uint4) with 8 fp32 activations (two float4)
__device__ __forceinline__ float dot8(uint4 wv, float4 x0, float4 x1) {
    float2 f0 = __bfloat1622float2(*(__nv_bfloat162*)&wv.x);
    float2 f1 = __bfloat1622float2(*(__nv_bfloat162*)&wv.y);
    float2 f2 = __bfloat1622float2(*(__nv_bfloat162*)&wv.z);
    float2 f3 = __bfloat1622float2(*(__nv_bfloat162*)&wv.w);
    return f0.x * x0.x + f0.y * x0.y + f1.x * x0.z + f1.y * x0.w
         + f2.x * x1.x + f2.y * x1.y + f3.x * x1.z + f3.y * x1.w;
}

// R12 grid barrier (measured-best): monotonic generation counter; release-add
// on arrive, last arriver release-stores d_gen, others acquire-spin.
// All cross-block traffic in recur_k uses __ldcg/__stcg (L2-coherent).
__device__ __forceinline__ void gridbar(unsigned &mygen) {
    __syncthreads();
    if (threadIdx.x == 0) {
        ++mygen;
        unsigned prev;
        asm volatile("atom.release.gpu.global.add.u32 %0, [%1], %2;"
                     : "=r"(prev) : "l"(&d_cnt), "r"(1u) : "memory");
        if (prev % NBLK == NBLK - 1) {
            asm volatile("st.release.gpu.global.u32 [%0], %1;"
                         :: "l"(&d_gen), "r"(mygen) : "memory");
        } else {
            unsigned g;
            do {
                asm volatile("ld.acquire.gpu.global.u32 %0, [%1];"
                             : "=r"(g) : "l"(&d_gen) : "memory");
            } while (g < mygen);
        }
    }
    __syncthreads();
}

// ---------------- init: state, pads, fused bias, barrier reset ----------------
__global__ void init_k(const float* __restrict__ b_ih, const float* __restrict__ b_hh) {
    int i = blockIdx.x * blockDim.x + threadIdx.x;
    if (i == 0) { d_cnt = 0u; d_gen = 0u; }
    if (i < STATE) { d_hx[0][i] = 0.f; d_hx[1][i] = 0.f; d_cx[i] = 0.f; }
    if (i < GATES) d_bihh[i] = b_ih[i] + b_hh[i];
    if (i < (NKBP - NKB)) d_w[NKB + i] = 0.f;
    if (i < (VALUE + 1) * (NKBP - NKB)) {
        int v = i / (NKBP - NKB);
        int n = NKB + i % (NKBP - NKB);
        d_kbvB[(size_t)v * NKBP + n] = __float2bfloat16(0.f);
    }
    if (i < NKB) d_kbvB[(size_t)VALUE * NKBP + i] = __float2bfloat16(1.f);
}

// ---------------- embedding gather ----------------
__global__ void embed_k(const int* __restrict__ ids, const float* __restrict__ encW) {
    int i = blockIdx.x * blockDim.x + threadIdx.x;
    if (i < SEQ * EMB) {
        int s = i >> 10, e = i & 1023;
        d_OUT[(size_t)s * DECIN + e] = encW[(size_t)ids[s] * EMB + e];
    }
}

// ---------------- fused one-time prep: transposes + bf16 conversions ----------------
__global__ void prep_k(const float* __restrict__ Wq1, const float* __restrict__ Wq2,
                       const float* __restrict__ kb_vals, const float* __restrict__ W_dec,
                       const float* __restrict__ kb_keys, const float* __restrict__ W_ih,
                       const float* __restrict__ W_hh) {
    const long stride = (long)gridDim.x * blockDim.x;
    const long t0 = (long)blockIdx.x * blockDim.x + threadIdx.x;
    // 1) Wq1T fp32 (PQ GEMM)
    for (long j = t0; j < (long)QIN * QIN; j += stride) {
        int r = (int)(j >> 11), c = (int)(j & (QIN - 1));
        d_Wq1T[j] = Wq1[(size_t)c * QIN + r];
    }
    // 2) Wq1B bf16: [r][k] = Wq1[k][r], k < 1024
    for (long j = t0; j < (long)QIN * STATE; j += stride) {
        int r = (int)(j >> 10), k = (int)(j & (STATE - 1));
        d_Wq1B[j] = __float2bfloat16(Wq1[(size_t)k * QIN + r]);
    }
    // 3) WhhB bf16 (no transpose)
    for (long j = t0; j < (long)GATES * STATE; j += stride)
        d_WhhB[j] = __float2bfloat16(W_hh[j]);
    // 4) Wq2B bf16: [k][jj] = Wq2[jj][k]
    for (long j = t0; j < (long)QUERY * QIN; j += stride) {
        int k = (int)(j >> 11), jj = (int)(j & (QIN - 1));
        d_Wq2B[j] = __float2bfloat16(Wq2[(size_t)jj * QUERY + k]);
    }
    // 5) kkB bf16 (no transpose)
    for (long j = t0; j < (long)NKB * QUERY; j += stride)
        d_kkB[j] = __float2bfloat16(kb_keys[j]);
    // 6) WivB bf16: [i][g][v] = W_ih[g*1024 + i][1024 + v]
    for (long j = t0; j < (long)STATE * 4 * VALUE; j += stride) {
        int i = (int)(j >> 11);
        int rem = (int)(j & 2047);
        int g = rem >> 9, v = rem & 511;
        d_WivB[j] = __float2bfloat16(W_ih[(size_t)(g * STATE + i) * LIN + EMB + v]);
    }
    // 7) kbvB bf16: [v][n] = kb_vals[n][v]
    for (long j = t0; j < (long)VALUE * NKB; j += stride) {
        int v = (int)(j / NKB), n = (int)(j % NKB);
        d_kbvB[(size_t)v * NKBP + n] = __float2bfloat16(kb_vals[(size_t)n * VALUE + v]);
    }
    // 8) W_dec -> bf16
    const float2* s2 = (const float2*)W_dec;
    __nv_bfloat162* dd = (__nv_bfloat162*)d_Wdbf;
    for (long j = t0; j < (long)NTOK * DECIN / 2; j += stride)
        dd[j] = __float22bfloat162_rn(s2[j]);
}

// ---------------- fp32 -> bf16 conversion (n even) ----------------
__global__ void tobf16_k(const float* __restrict__ S, __nv_bfloat16* __restrict__ D, long n) {
    const float2* s2 = (const float2*)S;
    __nv_bfloat162* d2 = (__nv_bfloat162*)D;
    long half = n >> 1;
    for (long j = (long)blockIdx.x * blockDim.x + threadIdx.x; j < half;
         j += (long)gridDim.x * blockDim.x)
        d2[j] = __float22bfloat162_rn(s2[j]);
}

// ---------------- fp32 SIMT SGEMM (phase-A only): C = bias + A @ B^T ----------------
__global__ void __launch_bounds__(256) gemm_abt(
    const float* __restrict__ A, int lda,
    const float* __restrict__ B, int ldb,
    const float* __restrict__ bias,
    float* __restrict__ C, int ldc, int K)
{
    __shared__ float As[16][132];
    __shared__ float Bs[16][132];
    const int tid = threadIdx.x;
    const int m0 = blockIdx.x * 128, n0 = blockIdx.y * 128;
    const int lr = tid >> 2;
    const int lk = (tid & 3) * 4;
    const int tx = tid & 15, ty = tid >> 4;

    float acc[8][8];
#pragma unroll
    for (int i = 0; i < 8; ++i)
#pragma unroll
        for (int j = 0; j < 8; ++j) acc[i][j] = 0.f;

    for (int k0 = 0; k0 < K; k0 += 16) {
#pragma unroll
        for (int h = 0; h < 2; ++h) {
            int r = lr + h * 64;
            float4 a = *(const float4*)&A[(size_t)(m0 + r) * lda + k0 + lk];
            As[lk + 0][r] = a.x; As[lk + 1][r] = a.y;
            As[lk + 2][r] = a.z; As[lk + 3][r] = a.w;
            float4 b = *(const float4*)&B[(size_t)(n0 + r) * ldb + k0 + lk];
            Bs[lk + 0][r] = b.x; Bs[lk + 1][r] = b.y;
            Bs[lk + 2][r] = b.z; Bs[lk + 3][r] = b.w;
        }
        __syncthreads();
#pragma unroll
        for (int kk = 0; kk < 16; ++kk) {
            float av[8], bv[8];
            const float4* a4 = (const float4*)&As[kk][ty * 8];
            const float4* b4 = (const float4*)&Bs[kk][tx * 8];
            float4 a0 = a4[0], a1 = a4[1];
            float4 b0 = b4[0], b1 = b4[1];
            av[0] = a0.x; av[1] = a0.y; av[2] = a0.z; av[3] = a0.w;
            av[4] = a1.x; av[5] = a1.y; av[6] = a1.z; av[7] = a1.w;
            bv[0] = b0.x; bv[1] = b0.y; bv[2] = b0.z; bv[3] = b0.w;
            bv[4] = b1.x; bv[5] = b1.y; bv[6] = b1.z; bv[7] = b1.w;
#pragma unroll
            for (int i = 0; i < 8; ++i)
#pragma unroll
                for (int j = 0; j < 8; ++j) acc[i][j] += av[i] * bv[j];
        }
        __syncthreads();
    }
#pragma unroll
    for (int i = 0; i < 8; ++i) {
        int row = m0 + ty * 8 + i;
#pragma unroll
        for (int j = 0; j < 8; ++j) {
            int col = n0 + tx * 8 + j;
            C[(size_t)row * ldc + col] = acc[i][j] + __ldg(&bias[col]);
        }
    }
}

// ---------------- bf16 tensor-core GEMM (decoder) ----------------
__global__ void __launch_bounds__(256) gemm_bf16_mma(
    const __nv_bfloat16* __restrict__ A, int lda,
    const __nv_bfloat16* __restrict__ B, int ldb,
    const float* __restrict__ bias,
    float* __restrict__ C, int ldc, int K)
{
    __shared__ unsigned As[128][17];
    __shared__ unsigned Bs[128][17];
    const int tid = threadIdx.x;
    const int wid = tid >> 5, lane = tid & 31;
    const int wm = wid & 3, wn = wid >> 2;
    const int m0 = blockIdx.x * 128, n0 = blockIdx.y * 128;
    const int r = lane >> 2, kp = lane & 3;

    float acc[2][8][4];
#pragma unroll
    for (int mt = 0; mt < 2; ++mt)
#pragma unroll
        for (int nt = 0; nt < 8; ++nt)
#pragma unroll
            for (int c = 0; c < 4; ++c) acc[mt][nt][c] = 0.f;

    for (int k0 = 0; k0 < K; k0 += 32) {
#pragma unroll
        for (int i = 0; i < 2; ++i) {
            int idx = tid + i * 256;
            int row = idx >> 2, q = idx & 3;
            uint4 va = *(const uint4*)&A[(size_t)(m0 + row) * lda + k0 + q * 8];
            As[row][q * 4 + 0] = va.x; As[row][q * 4 + 1] = va.y;
            As[row][q * 4 + 2] = va.z; As[row][q * 4 + 3] = va.w;
            uint4 vb = *(const uint4*)&B[(size_t)(n0 + row) * ldb + k0 + q * 8];
            Bs[row][q * 4 + 0] = vb.x; Bs[row][q * 4 + 1] = vb.y;
            Bs[row][q * 4 + 2] = vb.z; Bs[row][q * 4 + 3] = vb.w;
        }
        __syncthreads();
#pragma unroll
        for (int kk = 0; kk < 2; ++kk) {
            const int kb = kk * 8;
            unsigned afr[2][4];
#pragma unroll
            for (int mt = 0; mt < 2; ++mt) {
                int row = wm * 32 + mt * 16 + r;
                afr[mt][0] = As[row][kb + kp];
                afr[mt][1] = As[row + 8][kb + kp];
                afr[mt][2] = As[row][kb + kp + 4];
                afr[mt][3] = As[row + 8][kb + kp + 4];
            }
#pragma unroll
            for (int nt = 0; nt < 8; ++nt) {
                int brow = wn * 64 + nt * 8 + r;
                unsigned b0 = Bs[brow][kb + kp];
                unsigned b1 = Bs[brow][kb + kp + 4];
#pragma unroll
                for (int mt = 0; mt < 2; ++mt) {
                    asm volatile(
                        "mma.sync.aligned.m16n8k16.row.col.f32.bf16.bf16.f32 "
                        "{%0,%1,%2,%3}, {%4,%5,%6,%7}, {%8,%9}, {%0,%1,%2,%3};"
                        : "+f"(acc[mt][nt][0]), "+f"(acc[mt][nt][1]),
                          "+f"(acc[mt][nt][2]), "+f"(acc[mt][nt][3])
                        : "r"(afr[mt][0]), "r"(afr[mt][1]),
                          "r"(afr[mt][2]), "r"(afr[mt][3]),
                          "r"(b0), "r"(b1));
                }
            }
        }
        __syncthreads();
    }
#pragma unroll
    for (int mt = 0; mt < 2; ++mt) {
#pragma unroll
        for (int nt = 0; nt < 8; ++nt) {
            int row = m0 + wm * 32 + mt * 16 + r;
            int col = n0 + wn * 64 + nt * 8 + 2 * kp;
            float b0 = __ldg(&bias[col]), b1 = __ldg(&bias[col + 1]);
            *(float2*)&C[(size_t)row * ldc + col] =
                make_float2(acc[mt][nt][0] + b0, acc[mt][nt][1] + b1);
            *(float2*)&C[(size_t)(row + 8) * ldc + col] =
                make_float2(acc[mt][nt][2] + b0, acc[mt][nt][3] + b1);
        }
    }
}

// ---------------- persistent recurrence kernel (bf16 weights) ----------------
__global__ void __launch_bounds__(NTHR, 1) recur_k(const float* __restrict__ bq2)
{
    __shared__ __align__(16) float sb[NKBP];   // 40 KB staging buffer
    float4* sb4 = (float4*)sb;
    const int tid  = threadIdx.x;
    const int lane = tid & 31;
    const int wrp  = tid >> 5;
    const int W    = blockIdx.x * 16 + wrp;
    const int gid  = blockIdx.x * NTHR + tid;
    unsigned mygen = 0;

    for (int t = 0; t < SEQ; ++t) {
        const int p = t & 1;

        // ======== stage A: qh = tanh(PQ + hx@Wq1_hx); ghx = hx@W_hh.T ========
        if (tid < STATE / 4) sb4[tid] = __ldcg((const float4*)&d_hx[p][0] + tid);
        if (gid < QUERY)     d_qv[gid]   = 0.f;
        if (gid < VALUE + 1) d_valU[gid] = 0.f;
        __syncthreads();
        {
            const float* pq = d_PQ + (size_t)t * QIN;
            for (int r = W; r < QIN + GATES; r += NWTOT) {
                const uint4* wr4 = (r < QIN)
                    ? (const uint4*)(d_Wq1B + (size_t)r * STATE)
                    : (const uint4*)(d_WhhB + (size_t)(r - QIN) * STATE);
                float s = 0.f;
#pragma unroll
                for (int u = 0; u < 4; ++u) {
                    uint4 wv = __ldcg(&wr4[u * 32 + lane]);
                    int fi = (u * 32 + lane) * 2;
                    s += dot8(wv, sb4[fi], sb4[fi + 1]);
                }
                s = wred(s);
                if (lane == 0) {
                    if (r < QIN) __stcg(&d_qh[r], tanhf(__ldcg(&pq[r]) + s));
                    else         __stcg(&d_ghx[r - QIN], s);
                }
            }
        }
        gridbar(mygen);

        // ======== stage B: q = qh @ Wq2 + bq2 (8 x 256 chunks) ========
        for (int i = tid; i < QIN / 4; i += NTHR) sb4[i] = __ldcg((const float4*)d_qh + i);
        __syncthreads();
        for (int task = W; task < QUERY * 8; task += NWTOT) {
            int k = task >> 3, c = task & 7;
            const uint4* wr4 = (const uint4*)(d_Wq2B + (size_t)k * QIN + c * 256);
            uint4 wv = __ldcg(&wr4[lane]);
            int fi = c * 64 + lane * 2;
            float s = dot8(wv, sb4[fi], sb4[fi + 1]);
            s = wred(s);
            if (lane == 0) {
                if (c == 0) s += __ldg(&bq2[k]);
                atomicAdd(&d_qv[k], s);
            }
        }
        gridbar(mygen);

        // ======== stage C: w[n] = exp(kkB[n] . q); 2 rows/iter for MLP ========
        if (tid < QUERY / 4) sb4[tid] = __ldcg((const float4*)d_qv + tid);
        __syncthreads();
        {
            float4 q0 = sb4[lane * 2], q1 = sb4[lane * 2 + 1];
            for (int n = W; n < NKB; n += 2 * NWTOT) {
                int n1 = n + NWTOT;
                uint4 wv0 = __ldcg((const uint4*)(d_kkB + (size_t)n * QUERY) + lane);
                float s0, s1 = 0.f;
                if (n1 < NKB) {
                    uint4 wv1 = __ldcg((const uint4*)(d_kkB + (size_t)n1 * QUERY) + lane);
                    s1 = dot8(wv1, q0, q1);
                }
                s0 = dot8(wv0, q0, q1);
                s0 = wred(s0);
                s1 = wred(s1);
                if (lane == 0) {
                    __stcg(&d_w[n], expf(s0));
                    if (n1 < NKB) __stcg(&d_w[n1], expf(s1));
                }
            }
        }
        gridbar(mygen);

        // ======== stage D: valU[v] = w . kbvB[v]; valU[512] = sum w ========
        for (int i = tid; i < NKBP / 4; i += NTHR) sb4[i] = __ldcg((const float4*)d_w + i);
        __syncthreads();
        for (int task = W; task < (VALUE + 1) * 8; task += NWTOT) {
            int v = task >> 3, c = task & 7;
            const uint4* kr4 = (const uint4*)(d_kbvB + (size_t)v * NKBP + c * 1280);
            float s = 0.f;
#pragma unroll
            for (int u = 0; u < 5; ++u) {
                uint4 wv = __ldcg(&kr4[u * 32 + lane]);
                int fi = c * 320 + (u * 32 + lane) * 2;
                s += dot8(wv, sb4[fi], sb4[fi + 1]);
            }
            s = wred(s);
            if (lane == 0) atomicAdd(&d_valU[v], s);
        }
        gridbar(mygen);

        // ======== stage E: gates + LSTM pointwise + write OUT row ========
        if (tid < VALUE / 4) sb4[tid] = __ldcg((const float4*)d_valU + tid);
        if (tid == NTHR - 1) sb[VALUE] = __ldcg(&d_valU[VALUE]);
        __syncthreads();
        {
            const float inv = 1.f / sb[VALUE];
            float* outrow = d_OUT + (size_t)t * DECIN;
            const float* pi = d_PI + (size_t)t * GATES;
            for (int task = W; task < STATE + 16; task += NWTOT) {
                if (task < STATE) {
                    const int i = task;
                    const uint4* row = (const uint4*)(d_WivB + (size_t)i * 4 * VALUE);
                    float gs[4];
#pragma unroll
                    for (int g = 0; g < 4; ++g) {
                        float s = 0.f;
#pragma unroll
                        for (int u = 0; u < 2; ++u) {
                            uint4 wv = __ldcg(&row[g * 64 + u * 32 + lane]);
                            int fi = (u * 32 + lane) * 2;
                            s += dot8(wv, sb4[fi], sb4[fi + 1]);
                        }
                        gs[g] = wred(s);
                    }
                    if (lane == 0) {
                        float gi = __ldcg(&pi[i])             + __ldcg(&d_ghx[i])             + gs[0] * inv;
                        float gf = __ldcg(&pi[i + STATE])     + __ldcg(&d_ghx[i + STATE])     + gs[1] * inv;
                        float gG = __ldcg(&pi[i + 2 * STATE]) + __ldcg(&d_ghx[i + 2 * STATE]) + gs[2] * inv;
                        float go = __ldcg(&pi[i + 3 * STATE]) + __ldcg(&d_ghx[i + 3 * STATE]) + gs[3] * inv;
                        float hpre = __ldcg(&d_hx[p][i]);
                        float ii = 1.f / (1.f + expf(-gi));
                        float ff = 1.f / (1.f + expf(-gf));
                        float g2 = tanhf(gG);
                        float oo = 1.f / (1.f + expf(-go));
                        float cn = ff * __ldcg(&d_cx[i]) + ii * g2;
                        float hn = oo * tanhf(cn);
                        __stcg(&d_cx[i], cn);
                        __stcg(&d_hx[1 - p][i], hn);
                        outrow[EMB + VALUE + i] = hpre;
                    }
                } else {
                    int vb = (task - STATE) * 32 + lane;   // 16 warps x 32 = 512
                    outrow[EMB + vb] = sb[vb] * inv;
                }
            }
        }
        gridbar(mygen);
    }
}

// ---------------- row-wise log-softmax (in place) ----------------
__global__ void __launch_bounds__(256) logsoftmax_k(float* __restrict__ X) {
    const int row = blockIdx.x;
    float* x = X + (size_t)row * NTOK;
    __shared__ float sred[8];
    const int tid = threadIdx.x, lane = tid & 31, w = tid >> 5;

    float m = -1e30f;
    for (int i = tid; i < NTOK; i += 256) m = fmaxf(m, x[i]);
#pragma unroll
    for (int o = 16; o; o >>= 1) m = fmaxf(m, __shfl_xor_sync(0xffffffffu, m, o));
    if (lane == 0) sred[w] = m;
    __syncthreads();
    if (tid == 0) {
        float v = sred[0];
#pragma unroll
        for (int j = 1; j < 8; ++j) v = fmaxf(v, sred[j]);
        sred[0] = v;
    }
    __syncthreads();
    m = sred[0];
    __syncthreads();

    float s = 0.f;
    for (int i = tid; i < NTOK; i += 256) s += expf(x[i] - m);
    s = wred(s);
    if (lane == 0) sred[w] = s;
    __syncthreads();
    if (tid == 0) {
        float v = 0.f;
#pragma unroll
        for (int j = 0; j < 8; ++j) v += sred[j];
        sred[0] = v;
    }
    __syncthreads();
    const float lse = m + logf(sred[0]);

    for (int i = tid; i < NTOK; i += 256) x[i] = x[i] - lse;
}

// ---------------- launch ----------------
extern "C" void kernel_launch(void* const* d_in, const int* in_sizes, int n_in,
                              void* d_out, int out_size) {
    const int*   ids     = (const int*)  d_in[0];
    const float* enc_W   = (const float*)d_in[1];
    const float* Wq1     = (const float*)d_in[2];
    const float* bq1     = (const float*)d_in[3];
    const float* Wq2     = (const float*)d_in[4];
    const float* bq2     = (const float*)d_in[5];
    const float* kb_keys = (const float*)d_in[6];
    const float* kb_vals = (const float*)d_in[7];
    const float* W_ih    = (const float*)d_in[8];
    const float* b_ih    = (const float*)d_in[9];
    const float* W_hh    = (const float*)d_in[10];
    const float* b_hh    = (const float*)d_in[11];
    const float* W_dec   = (const float*)d_in[12];
    const float* b_dec   = (const float*)d_in[13];
    float* out = (float*)d_out;

    float* wq1t_dev = nullptr; cudaGetSymbolAddress((void**)&wq1t_dev, d_Wq1T);
    float* out_dev  = nullptr; cudaGetSymbolAddress((void**)&out_dev,  d_OUT);
    float* pq_dev   = nullptr; cudaGetSymbolAddress((void**)&pq_dev,   d_PQ);
    float* pi_dev   = nullptr; cudaGetSymbolAddress((void**)&pi_dev,   d_PI);
    float* bihh_dev = nullptr; cudaGetSymbolAddress((void**)&bihh_dev, d_bihh);
    __nv_bfloat16* abf_dev = nullptr; cudaGetSymbolAddress((void**)&abf_dev, d_Abf);
    __nv_bfloat16* wdb_dev = nullptr; cudaGetSymbolAddress((void**)&wdb_dev, d_Wdbf);

    // 1) init (state zero, pads, ones row, fused bias, barrier reset)
    init_k<<<((VALUE + 1) * (NKBP - NKB) + 255) / 256, 256>>>(b_ih, b_hh);
    // 2) embedding gather
    embed_k<<<(SEQ * EMB + 255) / 256, 256>>>(ids, enc_W);
    // 3) fused prep: fp32 transpose + all bf16 weight conversions
    prep_k<<<2048, 256>>>(Wq1, Wq2, kb_vals, W_dec, kb_keys, W_ih, W_hh);
    // 4) PQ = emb @ Wq1[x-part] + bq1
    gemm_abt<<<dim3(SEQ / 128, QIN / 128), 256>>>(
        out_dev, DECIN, wq1t_dev + EMB, QIN, bq1, pq_dev, QIN, EMB);
    // 5) PI = emb @ W_ih[:, :1024].T + (b_ih + b_hh)
    gemm_abt<<<dim3(SEQ / 128, GATES / 128), 256>>>(
        out_dev, DECIN, W_ih, LIN, bihh_dev, pi_dev, GATES, EMB);
    // 6) persistent recurrence (all weights prepped into device globals)
    recur_k<<<NBLK, NTHR>>>(bq2);
    // 7) OUT -> bf16, then tensor-core decoder GEMM
    tobf16_k<<<2048, 256>>>(out_dev, abf_dev, (long)SEQ * DECIN);
    gemm_bf16_mma<<<dim3(SEQ / 128, NTOK / 128), 256>>>(
        abf_dev, DECIN, wdb_dev, DECIN, b_dec, out, NTOK, DECIN);
    // 8) log-softmax in place
    logsoftmax_k<<<SEQ, 256>>>(out);
}